// round 13
// baseline (speedup 1.0000x reference)
#include <cuda_runtime.h>
#include <cstdint>

// FP4Quantizer, 2-node pipeline (no init kernel):
//   pass1 (grid up to 8192x256): scales ONLY. Each warp processes one group
//          of 4 blocks via 2x LDG.128; half-warp segmented REDUX/ballot
//          (masks 0xFFFF / 0xFFFF0000) — one collective instruction serves
//          two blocks. Exact top-5 per block (clear exactly one instance
//          per round). Fence-counter last-CTA publishes (smin, ss, rss).
//   pass2 (grid 4096x256): re-reads x (L2-hot), one quad per thread,
//          branchless bit-trick quantize-dequantize, streaming stores.

#define QBLK 64
#define MAX_QBLOCKS (262144 + 8192)
#define MAX_GRID1 8192
#define GRID2 4096
#define TPB   256

__device__ float2   g_bs[MAX_QBLOCKS];   // (inv_scale, scale)
__device__ unsigned g_pmin[MAX_GRID1];
__device__ unsigned g_pmax[MAX_GRID1];
__device__ unsigned g_ctr = 0;           // wraps to 0 every launch
__device__ float4   g_gmm;               // (smin, ss, rss, -)

__device__ __forceinline__ unsigned absbits(float f) {
    return __float_as_uint(f) & 0x7FFFFFFFu;
}

// CTA partial -> global publish -> last CTA computes (smin, ss, rss).
__device__ __forceinline__ void reduce_and_publish(unsigned mymin, unsigned mymax,
                                                   int tid, int lane, int w) {
    __shared__ unsigned s_rmin[TPB / 32], s_rmax[TPB / 32];
    __shared__ int s_last;
    mymin = __reduce_min_sync(0xFFFFFFFFu, mymin);
    mymax = __reduce_max_sync(0xFFFFFFFFu, mymax);
    if (lane == 0) { s_rmin[w] = mymin; s_rmax[w] = mymax; }
    __syncthreads();
    if (tid == 0) {
        unsigned a = 0xFFFFFFFFu, b = 0u;
        #pragma unroll
        for (int i = 0; i < TPB / 32; ++i) {
            a = a < s_rmin[i] ? a : s_rmin[i];
            b = b > s_rmax[i] ? b : s_rmax[i];
        }
        g_pmin[blockIdx.x] = a;
        g_pmax[blockIdx.x] = b;
        __threadfence();
        unsigned old = atomicInc(&g_ctr, gridDim.x - 1);  // wraps to 0 each launch
        s_last = (old == gridDim.x - 1);
    }
    __syncthreads();
    if (s_last) {
        unsigned lmin = 0xFFFFFFFFu, lmax = 0u;
        for (int i = tid; i < (int)gridDim.x; i += TPB) {
            unsigned a = __ldcg(&g_pmin[i]);
            unsigned b = __ldcg(&g_pmax[i]);
            lmin = lmin < a ? lmin : a;
            lmax = lmax > b ? lmax : b;
        }
        lmin = __reduce_min_sync(0xFFFFFFFFu, lmin);
        lmax = __reduce_max_sync(0xFFFFFFFFu, lmax);
        if (lane == 0) { s_rmin[w] = lmin; s_rmax[w] = lmax; }
        __syncthreads();
        if (tid == 0) {
            unsigned a = 0xFFFFFFFFu, b = 0u;
            #pragma unroll
            for (int i = 0; i < TPB / 32; ++i) {
                a = a < s_rmin[i] ? a : s_rmin[i];
                b = b > s_rmax[i] ? b : s_rmax[i];
            }
            float smin = __uint_as_float(a);
            float smax = __uint_as_float(b);
            bool  cond = smax > smin;
            float dd   = smax - smin;
            float ssc  = cond ? dd * (1.0f / 255.0f) : 1.0f;
            float rss  = cond ? 255.0f / dd : 0.0f;
            g_gmm = make_float4(smin, ssc, rss, 0.0f);
        }
    }
}

// ---------------- Pass 1 fast (n % 256 == 0) ----------------
// Group = 256 floats = 4 blocks. Lane holds float4 #lane (low half: block0,
// high half: block1) and float4 #(32+lane) (low: block2, high: block3).
// Each half-warp runs exact top-5 over its 16x4 values; two chains (per
// load) interleaved for ILP. One REDUX/ballot instruction serves 2 blocks.
// Rounds 3/4 give 4th/5th largest (sorted[60]/sorted[59]);
// quantile(0.95, 64) = s59 + 0.85*(s60 - s59).
__global__ void __launch_bounds__(TPB)
pass1_fast(const float* __restrict__ x, int ngroups) {
    const int tid  = threadIdx.x;
    const int lane = tid & 31;
    const int w    = tid >> 5;
    const int warp = (blockIdx.x * TPB + tid) >> 5;
    const int nw   = (gridDim.x * TPB) >> 5;
    const unsigned hmask = (lane < 16) ? 0x0000FFFFu : 0xFFFF0000u;
    unsigned mymin = 0xFFFFFFFFu, mymax = 0u;

    for (int g = warp; g < ngroups; g += nw) {
        const float4* __restrict__ x4 =
            reinterpret_cast<const float4*>(x + (long)g * 256);
        float4 p = x4[lane];        // chain P: block 4g + (lane>>4)
        float4 q = x4[32 + lane];   // chain Q: block 4g + 2 + (lane>>4)

        unsigned pa = absbits(p.x), pb = absbits(p.y);
        unsigned pc = absbits(p.z), pd = absbits(p.w);
        unsigned qa = absbits(q.x), qb = absbits(q.y);
        unsigned qc_ = absbits(q.z), qd = absbits(q.w);

        unsigned p4, p5, q4, q5;
        #pragma unroll
        for (int r = 0; r < 5; ++r) {
            unsigned pm = max(max(pa, pb), max(pc, pd));
            unsigned qm = max(max(qa, qb), max(qc_, qd));
            unsigned PW = __reduce_max_sync(hmask, pm);
            unsigned QW = __reduce_max_sync(hmask, qm);
            if (r == 3) { p4 = PW; q4 = QW; }
            if (r == 4) { p5 = PW; q5 = QW; }
            else {
                unsigned pbal = __ballot_sync(hmask, pm == PW);
                unsigned qbal = __ballot_sync(hmask, qm == QW);
                if (lane == __ffs((int)pbal) - 1) {
                    if      (pa == PW) pa = 0u;
                    else if (pb == PW) pb = 0u;
                    else if (pc == PW) pc = 0u;
                    else               pd = 0u;
                }
                if (lane == __ffs((int)qbal) - 1) {
                    if      (qa == QW) qa = 0u;
                    else if (qb == QW) qb = 0u;
                    else if (qc_ == QW) qc_ = 0u;
                    else                qd = 0u;
                }
            }
        }
        // p4/p5 (and q4/q5) are uniform within each half-warp.
        if ((lane & 15) == 0) {
            int half = lane >> 4;                 // 0 or 1
            float sP = fmaxf(fmaf(0.85f, __uint_as_float(p4) - __uint_as_float(p5),
                                  __uint_as_float(p5)), 1e-8f);
            float sQ = fmaxf(fmaf(0.85f, __uint_as_float(q4) - __uint_as_float(q5),
                                  __uint_as_float(q5)), 1e-8f);
            int blk = 4 * g + half;
            g_bs[blk]     = make_float2(1.0f / sP, sP);
            g_bs[blk + 2] = make_float2(1.0f / sQ, sQ);
            unsigned uP = __float_as_uint(sP), uQ = __float_as_uint(sQ);
            unsigned lo = uP < uQ ? uP : uQ;
            unsigned hi = uP > uQ ? uP : uQ;
            mymin = mymin < lo ? mymin : lo;
            mymax = mymax > hi ? mymax : hi;
        }
    }
    reduce_and_publish(mymin, mymax, tid, lane, w);
}

// ---------------- Pass 1 generic (any n) ----------------
__global__ void __launch_bounds__(TPB)
pass1_generic(const float* __restrict__ x, int n, int nblocks) {
    const int tid  = threadIdx.x;
    const int lane = tid & 31;
    const int w    = tid >> 5;
    const int warp = (blockIdx.x * TPB + tid) >> 5;
    const int nw   = (gridDim.x * TPB) >> 5;
    unsigned mymin = 0xFFFFFFFFu, mymax = 0u;

    for (int b = warp; b < nblocks; b += nw) {
        long base = (long)b * QBLK + lane * 2;
        float x0 = 0.0f, x1 = 0.0f;
        if (base + 1 < (long)n) {
            float2 t = *reinterpret_cast<const float2*>(x + base);
            x0 = t.x; x1 = t.y;
        } else if (base < (long)n) {
            x0 = x[base];
        }
        unsigned b0 = absbits(x0), b1 = absbits(x1);
        unsigned w4 = 0u, w5 = 0u;
        #pragma unroll
        for (int r = 0; r < 5; ++r) {
            unsigned m  = max(b0, b1);
            unsigned ww = __reduce_max_sync(0xFFFFFFFFu, m);
            if (r == 3) w4 = ww;
            if (r == 4) w5 = ww;
            else {
                unsigned bal = __ballot_sync(0xFFFFFFFFu, m == ww);
                if (lane == __ffs((int)bal) - 1) { if (b0 == ww) b0 = 0u; else b1 = 0u; }
            }
        }
        if (lane == 0) {
            float s = fmaxf(fmaf(0.85f, __uint_as_float(w4) - __uint_as_float(w5),
                                 __uint_as_float(w5)), 1e-8f);
            g_bs[b] = make_float2(1.0f / s, s);
            unsigned sb = __float_as_uint(s);
            mymin = mymin < sb ? mymin : sb;
            mymax = mymax > sb ? mymax : sb;
        }
    }
    reduce_and_publish(mymin, mymax, tid, lane, w);
}

// ---------------- Pass 2 ----------------
// Branchless nearest-level for {0, ±0.75, ±1, ±1.5, ±2, ±3}: round |x/s| to
// 1 mantissa bit, clamp [0.75, 3.0] as u32, zero at/below 0.375 (argmin
// tie-to-lower), multiply by deq, restore sign.
__device__ __forceinline__ float qdq_one(float xv, float inv, float deq) {
    float xs = xv * inv;
    unsigned ub = __float_as_uint(xs);
    unsigned uu = ub & 0x7FFFFFFFu;
    unsigned t  = (uu + 0x00200000u) & 0xFFC00000u;
    t = t < 0x40400000u ? t : 0x40400000u;
    t = t > 0x3F400000u ? t : 0x3F400000u;
    float lvl = (uu > 0x3EC00000u) ? __uint_as_float(t) : 0.0f;
    float o = lvl * deq;
    return __uint_as_float(__float_as_uint(o) | (ub & 0x80000000u));
}

// deq(s): double-quantized scale; rss==0 (degenerate) gives q=0 -> deq=0.
__device__ __forceinline__ float deq_of(float s, float smin, float rss, float ss) {
    float q = rintf((s - smin) * rss);
    q = fminf(fmaxf(q, 0.0f), 255.0f);
    return q * ss;
}

__global__ void __launch_bounds__(TPB)
pass2_kernel(const float* __restrict__ x, float* __restrict__ out, int n) {
    const int gtid = blockIdx.x * TPB + threadIdx.x;
    const int NT   = gridDim.x * TPB;
    const int nquads = n >> 2;

    float4 gmm = g_gmm;
    const float smin = gmm.x, ssc = gmm.y, rss = gmm.z;

    const float4* __restrict__ x4 = reinterpret_cast<const float4*>(x);
    float4* __restrict__ o4 = reinterpret_cast<float4*>(out);

    for (int q = gtid; q < nquads; q += NT) {
        float2 b = g_bs[q >> 4];
        float4 v = x4[q];
        float dq = deq_of(b.y, smin, rss, ssc);
        float4 r;
        r.x = qdq_one(v.x, b.x, dq);
        r.y = qdq_one(v.y, b.x, dq);
        r.z = qdq_one(v.z, b.x, dq);
        r.w = qdq_one(v.w, b.x, dq);
        __stcs(o4 + q, r);
    }
    // scalar tail (n not multiple of 4)
    for (int i = (nquads << 2) + gtid; i < n; i += NT) {
        float2 b = g_bs[i >> 6];
        float dq = deq_of(b.y, smin, rss, ssc);
        out[i] = qdq_one(x[i], b.x, dq);
    }
}

extern "C" void kernel_launch(void* const* d_in, const int* in_sizes, int n_in,
                              void* d_out, int out_size) {
    const float* x = (const float*)d_in[0];
    float* out = (float*)d_out;
    int n = in_sizes[0];

    if (((n & 255) == 0) && ((n >> 6) <= MAX_QBLOCKS)) {
        int ngroups = n >> 8;
        int warps_needed = ngroups;
        int ctas = (warps_needed + 7) / 8;             // 8 warps per CTA
        if (ctas > MAX_GRID1) ctas = MAX_GRID1;
        if (ctas < 1) ctas = 1;
        pass1_fast<<<ctas, TPB>>>(x, ngroups);
    } else {
        int nblocks = (n + QBLK - 1) / QBLK;
        pass1_generic<<<4096, TPB>>>(x, n, nblocks);
    }
    pass2_kernel<<<GRID2, TPB>>>(x, out, n);
}

// round 14
// speedup vs baseline: 1.3251x; 1.3251x over previous
#include <cuda_runtime.h>
#include <cstdint>

// FP4Quantizer, 2-node pipeline (no init kernel):
//   pass1 (grid 4096x256): scales ONLY. ILP-4 (4 blocks/warp-iteration),
//          software-pipelined prefetch (next group's loads issued before the
//          current group's collective chain), exact 5-REDUX/4-ballot top-5
//          per block with BRANCHLESS one-instance clears; fence-counter
//          last-CTA publishes (smin, ss, rss).
//   pass2 (grid 4096x256): re-reads x (L2-hot), one quad per thread,
//          branchless bit-trick quantize-dequantize, streaming stores.

#define QBLK 64
#define MAX_QBLOCKS (262144 + 8192)
#define GRID1 4096
#define GRID2 4096
#define TPB   256

__device__ float2   g_bs[MAX_QBLOCKS];   // (inv_scale, scale)
__device__ unsigned g_pmin[GRID1];
__device__ unsigned g_pmax[GRID1];
__device__ unsigned g_ctr = 0;           // wraps to 0 every launch
__device__ float4   g_gmm;               // (smin, ss, rss, -)

__device__ __forceinline__ unsigned absbits(float f) {
    return __float_as_uint(f) & 0x7FFFFFFFu;
}

// CTA partial -> global publish -> last CTA computes (smin, ss, rss).
__device__ __forceinline__ void reduce_and_publish(unsigned mymin, unsigned mymax,
                                                   int tid, int lane, int w) {
    __shared__ unsigned s_rmin[TPB / 32], s_rmax[TPB / 32];
    __shared__ int s_last;
    mymin = __reduce_min_sync(0xFFFFFFFFu, mymin);
    mymax = __reduce_max_sync(0xFFFFFFFFu, mymax);
    if (lane == 0) { s_rmin[w] = mymin; s_rmax[w] = mymax; }
    __syncthreads();
    if (tid == 0) {
        unsigned a = 0xFFFFFFFFu, b = 0u;
        #pragma unroll
        for (int i = 0; i < TPB / 32; ++i) {
            a = a < s_rmin[i] ? a : s_rmin[i];
            b = b > s_rmax[i] ? b : s_rmax[i];
        }
        g_pmin[blockIdx.x] = a;
        g_pmax[blockIdx.x] = b;
        __threadfence();
        unsigned old = atomicInc(&g_ctr, gridDim.x - 1);  // wraps to 0 each launch
        s_last = (old == gridDim.x - 1);
    }
    __syncthreads();
    if (s_last) {
        unsigned lmin = 0xFFFFFFFFu, lmax = 0u;
        for (int i = tid; i < (int)gridDim.x; i += TPB) {
            unsigned a = __ldcg(&g_pmin[i]);
            unsigned b = __ldcg(&g_pmax[i]);
            lmin = lmin < a ? lmin : a;
            lmax = lmax > b ? lmax : b;
        }
        lmin = __reduce_min_sync(0xFFFFFFFFu, lmin);
        lmax = __reduce_max_sync(0xFFFFFFFFu, lmax);
        if (lane == 0) { s_rmin[w] = lmin; s_rmax[w] = lmax; }
        __syncthreads();
        if (tid == 0) {
            unsigned a = 0xFFFFFFFFu, b = 0u;
            #pragma unroll
            for (int i = 0; i < TPB / 32; ++i) {
                a = a < s_rmin[i] ? a : s_rmin[i];
                b = b > s_rmax[i] ? b : s_rmax[i];
            }
            float smin = __uint_as_float(a);
            float smax = __uint_as_float(b);
            bool  cond = smax > smin;
            float dd   = smax - smin;
            float ssc  = cond ? dd * (1.0f / 255.0f) : 1.0f;
            float rss  = cond ? 255.0f / dd : 0.0f;
            g_gmm = make_float4(smin, ssc, rss, 0.0f);
        }
    }
}

// ---------------- Pass 1 fast (n % 256 == 0) ----------------
// One warp handles 4 blocks per iteration; next iteration's 4 loads are
// issued BEFORE the current collective chain (prefetch pipeline). Exact
// top-5 per block: 5 full-warp REDUX rounds; rounds 0-3 ballot-clear
// exactly ONE instance (branchless all-lane SEL). Rounds 3/4 give the
// 4th/5th largest (sorted[60]/sorted[59]);
// quantile(0.95, 64) = s59 + 0.85*(s60 - s59).
__global__ void __launch_bounds__(TPB)
pass1_fast(const float* __restrict__ x, int ngroups) {
    const int tid  = threadIdx.x;
    const int lane = tid & 31;
    const int w    = tid >> 5;
    const int warp = (blockIdx.x * TPB + tid) >> 5;
    const int nw   = (gridDim.x * TPB) >> 5;
    unsigned mymin = 0xFFFFFFFFu, mymax = 0u;

    int g = warp;
    float2 v0, v1, v2, v3;
    if (g < ngroups) {
        const float2* __restrict__ x2 =
            reinterpret_cast<const float2*>(x + (long)g * 256);
        v0 = x2[lane]; v1 = x2[32 + lane]; v2 = x2[64 + lane]; v3 = x2[96 + lane];
    }
    while (g < ngroups) {
        const int gn = g + nw;
        float2 t0 = make_float2(0.f, 0.f), t1 = t0, t2 = t0, t3 = t0;
        if (gn < ngroups) {                 // prefetch: in flight during chain
            const float2* __restrict__ xn =
                reinterpret_cast<const float2*>(x + (long)gn * 256);
            t0 = xn[lane]; t1 = xn[32 + lane]; t2 = xn[64 + lane]; t3 = xn[96 + lane];
        }

        unsigned A0 = absbits(v0.x), B0 = absbits(v0.y);
        unsigned A1 = absbits(v1.x), B1 = absbits(v1.y);
        unsigned A2 = absbits(v2.x), B2 = absbits(v2.y);
        unsigned A3 = absbits(v3.x), B3 = absbits(v3.y);

        unsigned w40, w41, w42, w43, w50, w51, w52, w53;
        #pragma unroll
        for (int r = 0; r < 5; ++r) {
            unsigned m0 = max(A0, B0), m1 = max(A1, B1);
            unsigned m2 = max(A2, B2), m3 = max(A3, B3);
            unsigned W0 = __reduce_max_sync(0xFFFFFFFFu, m0);
            unsigned W1 = __reduce_max_sync(0xFFFFFFFFu, m1);
            unsigned W2 = __reduce_max_sync(0xFFFFFFFFu, m2);
            unsigned W3 = __reduce_max_sync(0xFFFFFFFFu, m3);
            if (r == 3) { w40 = W0; w41 = W1; w42 = W2; w43 = W3; }
            if (r == 4) { w50 = W0; w51 = W1; w52 = W2; w53 = W3; }
            else {
                unsigned bl0 = __ballot_sync(0xFFFFFFFFu, m0 == W0);
                unsigned bl1 = __ballot_sync(0xFFFFFFFFu, m1 == W1);
                unsigned bl2 = __ballot_sync(0xFFFFFFFFu, m2 == W2);
                unsigned bl3 = __ballot_sync(0xFFFFFFFFu, m3 == W3);
                // branchless clear-exactly-one (leader lane; A first, else B)
                bool L0 = (lane == __ffs((int)bl0) - 1);
                bool L1 = (lane == __ffs((int)bl1) - 1);
                bool L2 = (lane == __ffs((int)bl2) - 1);
                bool L3 = (lane == __ffs((int)bl3) - 1);
                bool cA0 = L0 && (A0 == W0);
                bool cA1 = L1 && (A1 == W1);
                bool cA2 = L2 && (A2 == W2);
                bool cA3 = L3 && (A3 == W3);
                A0 = cA0 ? 0u : A0;  B0 = (L0 && !cA0) ? 0u : B0;
                A1 = cA1 ? 0u : A1;  B1 = (L1 && !cA1) ? 0u : B1;
                A2 = cA2 ? 0u : A2;  B2 = (L2 && !cA2) ? 0u : B2;
                A3 = cA3 ? 0u : A3;  B3 = (L3 && !cA3) ? 0u : B3;
            }
        }
        if (lane == 0) {
            float s0 = fmaxf(fmaf(0.85f, __uint_as_float(w40) - __uint_as_float(w50),
                                  __uint_as_float(w50)), 1e-8f);
            float s1 = fmaxf(fmaf(0.85f, __uint_as_float(w41) - __uint_as_float(w51),
                                  __uint_as_float(w51)), 1e-8f);
            float s2 = fmaxf(fmaf(0.85f, __uint_as_float(w42) - __uint_as_float(w52),
                                  __uint_as_float(w52)), 1e-8f);
            float s3 = fmaxf(fmaf(0.85f, __uint_as_float(w43) - __uint_as_float(w53),
                                  __uint_as_float(w53)), 1e-8f);
            int blk = 4 * g;
            float4* bs4 = reinterpret_cast<float4*>(&g_bs[blk]);
            bs4[0] = make_float4(1.0f / s0, s0, 1.0f / s1, s1);
            bs4[1] = make_float4(1.0f / s2, s2, 1.0f / s3, s3);
            unsigned u0 = __float_as_uint(s0), u1 = __float_as_uint(s1);
            unsigned u2 = __float_as_uint(s2), u3 = __float_as_uint(s3);
            unsigned lo = min(min(u0, u1), min(u2, u3));
            unsigned hi = max(max(u0, u1), max(u2, u3));
            mymin = mymin < lo ? mymin : lo;
            mymax = mymax > hi ? mymax : hi;
        }
        g = gn;
        v0 = t0; v1 = t1; v2 = t2; v3 = t3;
    }
    reduce_and_publish(mymin, mymax, tid, lane, w);
}

// ---------------- Pass 1 generic (any n) ----------------
__global__ void __launch_bounds__(TPB)
pass1_generic(const float* __restrict__ x, int n, int nblocks) {
    const int tid  = threadIdx.x;
    const int lane = tid & 31;
    const int w    = tid >> 5;
    const int warp = (blockIdx.x * TPB + tid) >> 5;
    const int nw   = (gridDim.x * TPB) >> 5;
    unsigned mymin = 0xFFFFFFFFu, mymax = 0u;

    for (int b = warp; b < nblocks; b += nw) {
        long base = (long)b * QBLK + lane * 2;
        float x0 = 0.0f, x1 = 0.0f;
        if (base + 1 < (long)n) {
            float2 t = *reinterpret_cast<const float2*>(x + base);
            x0 = t.x; x1 = t.y;
        } else if (base < (long)n) {
            x0 = x[base];
        }
        unsigned b0 = absbits(x0), b1 = absbits(x1);
        unsigned w4 = 0u, w5 = 0u;
        #pragma unroll
        for (int r = 0; r < 5; ++r) {
            unsigned m  = max(b0, b1);
            unsigned ww = __reduce_max_sync(0xFFFFFFFFu, m);
            if (r == 3) w4 = ww;
            if (r == 4) w5 = ww;
            else {
                unsigned bal = __ballot_sync(0xFFFFFFFFu, m == ww);
                bool L  = (lane == __ffs((int)bal) - 1);
                bool cA = L && (b0 == ww);
                b0 = cA ? 0u : b0;
                b1 = (L && !cA) ? 0u : b1;
            }
        }
        if (lane == 0) {
            float s = fmaxf(fmaf(0.85f, __uint_as_float(w4) - __uint_as_float(w5),
                                 __uint_as_float(w5)), 1e-8f);
            g_bs[b] = make_float2(1.0f / s, s);
            unsigned sb = __float_as_uint(s);
            mymin = mymin < sb ? mymin : sb;
            mymax = mymax > sb ? mymax : sb;
        }
    }
    reduce_and_publish(mymin, mymax, tid, lane, w);
}

// ---------------- Pass 2 ----------------
// Branchless nearest-level for {0, ±0.75, ±1, ±1.5, ±2, ±3}: round |x/s| to
// 1 mantissa bit, clamp [0.75, 3.0] as u32, zero at/below 0.375 (argmin
// tie-to-lower), multiply by deq, restore sign.
__device__ __forceinline__ float qdq_one(float xv, float inv, float deq) {
    float xs = xv * inv;
    unsigned ub = __float_as_uint(xs);
    unsigned uu = ub & 0x7FFFFFFFu;
    unsigned t  = (uu + 0x00200000u) & 0xFFC00000u;
    t = t < 0x40400000u ? t : 0x40400000u;
    t = t > 0x3F400000u ? t : 0x3F400000u;
    float lvl = (uu > 0x3EC00000u) ? __uint_as_float(t) : 0.0f;
    float o = lvl * deq;
    return __uint_as_float(__float_as_uint(o) | (ub & 0x80000000u));
}

// deq(s): double-quantized scale; rss==0 (degenerate) gives q=0 -> deq=0.
__device__ __forceinline__ float deq_of(float s, float smin, float rss, float ss) {
    float q = rintf((s - smin) * rss);
    q = fminf(fmaxf(q, 0.0f), 255.0f);
    return q * ss;
}

__global__ void __launch_bounds__(TPB)
pass2_kernel(const float* __restrict__ x, float* __restrict__ out, int n) {
    const int gtid = blockIdx.x * TPB + threadIdx.x;
    const int NT   = gridDim.x * TPB;
    const int nquads = n >> 2;

    float4 gmm = g_gmm;
    const float smin = gmm.x, ssc = gmm.y, rss = gmm.z;

    const float4* __restrict__ x4 = reinterpret_cast<const float4*>(x);
    float4* __restrict__ o4 = reinterpret_cast<float4*>(out);

    for (int q = gtid; q < nquads; q += NT) {
        float2 b = g_bs[q >> 4];
        float4 v = x4[q];
        float dq = deq_of(b.y, smin, rss, ssc);
        float4 r;
        r.x = qdq_one(v.x, b.x, dq);
        r.y = qdq_one(v.y, b.x, dq);
        r.z = qdq_one(v.z, b.x, dq);
        r.w = qdq_one(v.w, b.x, dq);
        __stcs(o4 + q, r);
    }
    // scalar tail (n not multiple of 4)
    for (int i = (nquads << 2) + gtid; i < n; i += NT) {
        float2 b = g_bs[i >> 6];
        float dq = deq_of(b.y, smin, rss, ssc);
        out[i] = qdq_one(x[i], b.x, dq);
    }
}

extern "C" void kernel_launch(void* const* d_in, const int* in_sizes, int n_in,
                              void* d_out, int out_size) {
    const float* x = (const float*)d_in[0];
    float* out = (float*)d_out;
    int n = in_sizes[0];

    if (((n & 255) == 0) && ((n >> 6) <= MAX_QBLOCKS)) {
        pass1_fast<<<GRID1, TPB>>>(x, n >> 8);
    } else {
        int nblocks = (n + QBLK - 1) / QBLK;
        pass1_generic<<<GRID1, TPB>>>(x, n, nblocks);
    }
    pass2_kernel<<<GRID2, TPB>>>(x, out, n);
}